// round 3
// baseline (speedup 1.0000x reference)
#include <cuda_runtime.h>
#include <cstring>

// Problem constants (shapes are fixed by the reference).
#define NF      128     // NUM_FEATURES
#define NR      6       // NUM_RADIAL
#define K3F     384     // 3 * NF
#define TILE_E  64      // edges per CTA tile
#define NTHREADS 256
#define HSTRIDE 388     // h row stride in floats (384 + 4 pad: kills bank aliasing, keeps 16B align)

// smem float layout:
//   h      : [TILE_E * HSTRIDE]            = 24832 floats
//   zi     : [TILE_E] (as int)             = 64
//   zj     : [TILE_E] (as int)             = 64
//   rbf_s  : [TILE_E * NR]                 = 384
#define SM_H      0
#define SM_ZI     (TILE_E * HSTRIDE)
#define SM_ZJ     (SM_ZI + TILE_E)
#define SM_RBF    (SM_ZJ + TILE_E)
#define SM_FLOATS (SM_RBF + TILE_E * NR)    // 25344 floats = 101376 bytes

__device__ __forceinline__ float swishf(float x) {
    // x * sigmoid(x) = x / (1 + e^-x). Fast-math variants are ~2 ulp: fine vs 1e-3.
    return __fdividef(x, 1.0f + __expf(-x));
}

// Packed f32x2 FMA — Blackwell-only, NOT emitted by ptxas from C++ (see SASS_QUICKREF).
__device__ __forceinline__ unsigned long long fma2(unsigned long long a,
                                                   unsigned long long b,
                                                   unsigned long long c) {
    unsigned long long d;
    asm("fma.rn.f32x2 %0, %1, %2, %3;" : "=l"(d) : "l"(a), "l"(b), "l"(c));
    return d;
}

__device__ __forceinline__ unsigned long long pk2(float v) {
    float2 t = make_float2(v, v);
    unsigned long long u;
    memcpy(&u, &t, 8);
    return u;
}

union F4U { float4 f; unsigned long long u[2]; };
union F2U { float2 f; unsigned long long u; };

__global__ void __launch_bounds__(NTHREADS, 2)
embedding_block_kernel(const int* __restrict__ Z,
                       const float* __restrict__ rbf,
                       const int* __restrict__ idnb_i,
                       const int* __restrict__ idnb_j,
                       const float* __restrict__ emb,
                       const float* __restrict__ W_rbf,
                       const float* __restrict__ b_rbf,
                       const float* __restrict__ W,
                       const float* __restrict__ bias,
                       float* __restrict__ out,
                       int E) {
    extern __shared__ float smem[];
    float* h_s   = smem + SM_H;
    int*   zi_s  = (int*)(smem + SM_ZI);
    int*   zj_s  = (int*)(smem + SM_ZJ);
    float* rbf_s = smem + SM_RBF;

    const int tid  = threadIdx.x;
    const int base = blockIdx.x * TILE_E;

    // ---- Stage per-edge scalars: indices -> Z gathers, rbf rows ----
    if (tid < TILE_E) {
        int eg = base + tid;
        int ec = (eg < E) ? eg : (E - 1);
        int i = idnb_i[ec];
        int j = idnb_j[ec];
        zi_s[tid] = Z[i];
        zj_s[tid] = Z[j];
        #pragma unroll
        for (int r = 0; r < NR; r++)
            rbf_s[tid * NR + r] = rbf[(size_t)ec * NR + r];
    }
    __syncthreads();

    // ---- Phase 1: build h tile [TILE_E][384] in smem ----
    // idx enumerates (edge, float4-column): 64 * 32 = 2048 slots, 8 per thread.
    // Within a warp: e is constant, c = lane -> fully coalesced gathers + conflict-free STS.
    for (int idx = tid; idx < TILE_E * (NF / 4); idx += NTHREADS) {
        int e = idx >> 5;          // edge within tile
        int c = idx & 31;          // float4 column (0..31)
        int zi = zi_s[e];
        int zj = zj_s[e];
        float4 a1 = *(const float4*)(emb + zi * NF + c * 4);
        float4 a2 = *(const float4*)(emb + zj * NF + c * 4);
        float* hrow = h_s + e * HSTRIDE;
        *(float4*)(hrow + c * 4)      = a1;
        *(float4*)(hrow + NF + c * 4) = a2;

        // rbf_h for features [4c, 4c+4): 6-term dense + swish
        float4 acc = *(const float4*)(b_rbf + c * 4);
        #pragma unroll
        for (int r = 0; r < NR; r++) {
            float rv = rbf_s[e * NR + r];
            float4 w = *(const float4*)(W_rbf + r * NF + c * 4);
            acc.x = fmaf(rv, w.x, acc.x);
            acc.y = fmaf(rv, w.y, acc.y);
            acc.z = fmaf(rv, w.z, acc.z);
            acc.w = fmaf(rv, w.w, acc.w);
        }
        acc.x = swishf(acc.x); acc.y = swishf(acc.y);
        acc.z = swishf(acc.z); acc.w = swishf(acc.w);
        *(float4*)(hrow + 2 * NF + c * 4) = acc;
    }
    __syncthreads();

    // ---- Phase 2: out[e][f] = swish(h[e][:] @ W[:, f] + b[f]) ----
    // Thread = (tx: 8 features) x (ty: 4 edges). 16 x 16 = 256 threads, 64 edges, 128 feats.
    const int tx = tid & 15;   // feature group: f = tx*8 .. tx*8+7
    const int ty = tid >> 4;   // edge group:    e = ty*4 .. ty*4+3

    unsigned long long acc[4][4];   // [edge][f32x2 pair]
    #pragma unroll
    for (int e = 0; e < 4; e++)
        #pragma unroll
        for (int p = 0; p < 4; p++)
            acc[e][p] = 0ULL;

    const float* Wp = W + tx * 8;                   // row k: Wp + k*NF
    const float* hb = h_s + (ty * 4) * HSTRIDE;     // edges ty*4 ..

    #pragma unroll 4
    for (int k = 0; k < K3F; k += 2) {
        // W rows k and k+1, 8 features each -> 4 f32x2 pairs per row
        F4U wA0, wA1, wB0, wB1;
        wA0.f = *(const float4*)(Wp + (size_t)k * NF);
        wA1.f = *(const float4*)(Wp + (size_t)k * NF + 4);
        wB0.f = *(const float4*)(Wp + (size_t)(k + 1) * NF);
        wB1.f = *(const float4*)(Wp + (size_t)(k + 1) * NF + 4);

        #pragma unroll
        for (int e = 0; e < 4; e++) {
            float2 hv = *(const float2*)(hb + e * HSTRIDE + k);  // h[e][k], h[e][k+1]
            unsigned long long ha = pk2(hv.x);
            unsigned long long hbk = pk2(hv.y);
            acc[e][0] = fma2(ha, wA0.u[0], acc[e][0]);
            acc[e][1] = fma2(ha, wA0.u[1], acc[e][1]);
            acc[e][2] = fma2(ha, wA1.u[0], acc[e][2]);
            acc[e][3] = fma2(ha, wA1.u[1], acc[e][3]);
            acc[e][0] = fma2(hbk, wB0.u[0], acc[e][0]);
            acc[e][1] = fma2(hbk, wB0.u[1], acc[e][1]);
            acc[e][2] = fma2(hbk, wB1.u[0], acc[e][2]);
            acc[e][3] = fma2(hbk, wB1.u[1], acc[e][3]);
        }
    }

    // ---- Epilogue: + bias, swish, coalesced stores ----
    float4 b0 = *(const float4*)(bias + tx * 8);
    float4 b1 = *(const float4*)(bias + tx * 8 + 4);

    #pragma unroll
    for (int e = 0; e < 4; e++) {
        int eg = base + ty * 4 + e;
        if (eg >= E) continue;
        F2U p0, p1, p2, p3;
        p0.u = acc[e][0]; p1.u = acc[e][1];
        p2.u = acc[e][2]; p3.u = acc[e][3];
        float4 o0, o1;
        o0.x = swishf(p0.f.x + b0.x);
        o0.y = swishf(p0.f.y + b0.y);
        o0.z = swishf(p1.f.x + b0.z);
        o0.w = swishf(p1.f.y + b0.w);
        o1.x = swishf(p2.f.x + b1.x);
        o1.y = swishf(p2.f.y + b1.y);
        o1.z = swishf(p3.f.x + b1.z);
        o1.w = swishf(p3.f.y + b1.w);
        float* op = out + (size_t)eg * NF + tx * 8;
        *(float4*)(op)     = o0;
        *(float4*)(op + 4) = o1;
    }
}

extern "C" void kernel_launch(void* const* d_in, const int* in_sizes, int n_in,
                              void* d_out, int out_size) {
    const int*   Z      = (const int*)  d_in[0];
    const float* rbf    = (const float*)d_in[1];
    const int*   idnb_i = (const int*)  d_in[2];
    const int*   idnb_j = (const int*)  d_in[3];
    const float* emb    = (const float*)d_in[4];
    const float* W_rbf  = (const float*)d_in[5];
    const float* b_rbf  = (const float*)d_in[6];
    const float* W      = (const float*)d_in[7];
    const float* bias   = (const float*)d_in[8];
    float* out = (float*)d_out;

    const int E = in_sizes[2];  // number of edges (idnb_i length)
    const int smem_bytes = SM_FLOATS * (int)sizeof(float);  // 101376 B

    // > 48 KB dynamic smem requires explicit opt-in (attribute set is not a
    // stream op; safe under graph capture, idempotent across calls).
    cudaFuncSetAttribute(embedding_block_kernel,
                         cudaFuncAttributeMaxDynamicSharedMemorySize, smem_bytes);

    const int grid = (E + TILE_E - 1) / TILE_E;
    embedding_block_kernel<<<grid, NTHREADS, smem_bytes>>>(
        Z, rbf, idnb_i, idnb_j, emb, W_rbf, b_rbf, W, bias, out, E);
}

// round 7
// speedup vs baseline: 2.0834x; 2.0834x over previous
#include <cuda_runtime.h>
#include <cuda_bf16.h>
#include <cstdint>
#include <cstring>

// ---------------- Problem constants ----------------
#define NF      128      // NUM_FEATURES
#define NR      6        // NUM_RADIAL
#define TILE_E  128      // edges per CTA (= GEMM M)
#define KC      64       // K per chunk
#define NCHUNK  6        // 384 / 64
#define NTH     256
#define PK      72       // padded smem row stride in bf16 (144 B) -> conflict-free ldmatrix

// ---------------- smem layout (bytes) ----------------
// 4 tiles [128 rows][PK bf16]: A_hi, A_lo (h tile), B_hi, B_lo (W^T tile)
#define TBYTES  (128 * PK * 2)          // 18432
#define SM_AHI  0
#define SM_ALO  (SM_AHI + TBYTES)
#define SM_BHI  (SM_ALO + TBYTES)
#define SM_BLO  (SM_BHI + TBYTES)
#define SM_ZI   (SM_BLO + TBYTES)       // int[128]
#define SM_ZJ   (SM_ZI + 512)
#define SM_RBF  (SM_ZJ + 512)           // float[128*6]
#define SM_BYTES (SM_RBF + 3072)        // 77824 B

// W split + transpose, produced by prep kernel: [chunk][n=128][kk=64] bf16
__device__ __align__(16) __nv_bfloat16 g_WT_hi[NCHUNK * 128 * KC];
__device__ __align__(16) __nv_bfloat16 g_WT_lo[NCHUNK * 128 * KC];

// ---------------- helpers ----------------
__device__ __forceinline__ uint32_t smem_u32(const void* p) {
    uint32_t a;
    asm("{ .reg .u64 t; cvta.to.shared.u64 t, %1; cvt.u32.u64 %0, t; }"
        : "=r"(a) : "l"(p));
    return a;
}

__device__ __forceinline__ float swishf(float x) {
    return __fdividef(x, 1.0f + __expf(-x));
}

__device__ __forceinline__ void ldsm4(uint32_t addr, uint32_t& r0, uint32_t& r1,
                                      uint32_t& r2, uint32_t& r3) {
    asm volatile("ldmatrix.sync.aligned.m8n8.x4.shared.b16 {%0,%1,%2,%3}, [%4];"
                 : "=r"(r0), "=r"(r1), "=r"(r2), "=r"(r3) : "r"(addr));
}

__device__ __forceinline__ void mma_bf16(float* c, uint32_t a0, uint32_t a1,
                                         uint32_t a2, uint32_t a3,
                                         uint32_t b0, uint32_t b1) {
    asm volatile(
        "mma.sync.aligned.m16n8k16.row.col.f32.bf16.bf16.f32 "
        "{%0,%1,%2,%3}, {%4,%5,%6,%7}, {%8,%9}, {%0,%1,%2,%3};"
        : "+f"(c[0]), "+f"(c[1]), "+f"(c[2]), "+f"(c[3])
        : "r"(a0), "r"(a1), "r"(a2), "r"(a3), "r"(b0), "r"(b1));
}

// Split 4 fp32 -> bf16 hi/lo pairs; store 8B each into padded-stride tiles.
__device__ __forceinline__ void store_split(float4 v, char* hi, char* lo, int bo) {
    __nv_bfloat162 h0 = __float22bfloat162_rn(make_float2(v.x, v.y));
    __nv_bfloat162 h1 = __float22bfloat162_rn(make_float2(v.z, v.w));
    float2 f0 = __bfloat1622float2(h0);
    float2 f1 = __bfloat1622float2(h1);
    __nv_bfloat162 l0 = __float22bfloat162_rn(make_float2(v.x - f0.x, v.y - f0.y));
    __nv_bfloat162 l1 = __float22bfloat162_rn(make_float2(v.z - f1.x, v.w - f1.y));
    uint2 hp, lp;
    memcpy(&hp.x, &h0, 4); memcpy(&hp.y, &h1, 4);
    memcpy(&lp.x, &l0, 4); memcpy(&lp.y, &l1, 4);
    *(uint2*)(hi + bo) = hp;
    *(uint2*)(lo + bo) = lp;
}

// ---------------- Prep: W[384,128] -> WT hi/lo [chunk][n][kk] ----------------
__global__ void prep_w_kernel(const float* __restrict__ W) {
    int idx = blockIdx.x * blockDim.x + threadIdx.x;   // [c][n][kk], kk fastest
    if (idx >= NCHUNK * 128 * KC) return;
    int kk = idx & (KC - 1);
    int n  = (idx >> 6) & 127;
    int c  = idx >> 13;
    float v = W[(c * KC + kk) * NF + n];
    __nv_bfloat16 h = __float2bfloat16(v);
    float l = v - __bfloat162float(h);
    g_WT_hi[idx] = h;
    g_WT_lo[idx] = __float2bfloat16(l);
}

// ---------------- Main kernel ----------------
__global__ void __launch_bounds__(NTH, 1)
embedding_block_mma(const int* __restrict__ Z,
                    const float* __restrict__ rbf,
                    const int* __restrict__ idnb_i,
                    const int* __restrict__ idnb_j,
                    const float* __restrict__ emb,
                    const float* __restrict__ W_rbf,
                    const float* __restrict__ b_rbf,
                    const float* __restrict__ bias,
                    float* __restrict__ out,
                    int E) {
    extern __shared__ char smem[];
    const uint32_t sbase = smem_u32(smem);
    const int tid  = threadIdx.x;
    const int lane = tid & 31;
    const int wid  = tid >> 5;
    const int wm   = wid & 3;          // warp M position: rows wm*32 .. +31
    const int wn   = wid >> 2;         // warp N position: cols wn*64 .. +63
    const int base = blockIdx.x * TILE_E;

    int*   zi_s  = (int*)(smem + SM_ZI);
    int*   zj_s  = (int*)(smem + SM_ZJ);
    float* rbf_s = (float*)(smem + SM_RBF);

    // ---- stage per-edge scalars ----
    if (tid < TILE_E) {
        int eg = base + tid;
        int ec = (eg < E) ? eg : (E - 1);
        zi_s[tid] = Z[idnb_i[ec]];
        zj_s[tid] = Z[idnb_j[ec]];
        #pragma unroll
        for (int r = 0; r < NR; r++)
            rbf_s[tid * NR + r] = rbf[(size_t)ec * NR + r];
    }
    __syncthreads();

    // ---- per-thread build-phase ids ----
    const int be = tid >> 1;            // row (edge for A / feature n for B)
    const int kh = (tid & 1) * 32;      // k sub-range within chunk

    // ---- per-thread ldmatrix address components ----
    // A (m16k16, x4): row = mbase + (lane&15), kcol = k0 + ((lane&16)>>1)
    const int a_row = wm * 32 + (lane & 15);
    const int a_kad = (lane & 16) >> 1;
    // B (n16k16, x4): row = nbase + (lane&7) + ((lane&16)>>1), kcol = k0 + (lane&8)
    const int b_row = wn * 64 + (lane & 7) + ((lane & 16) >> 1);
    const int b_kad = lane & 8;

    const uint32_t ahi_b = sbase + SM_AHI, alo_b = sbase + SM_ALO;
    const uint32_t bhi_b = sbase + SM_BHI, blo_b = sbase + SM_BLO;

    // accumulators: [mi 2][ni 8][4]
    float acc[2][8][4];
    #pragma unroll
    for (int mi = 0; mi < 2; mi++)
        #pragma unroll
        for (int ni = 0; ni < 8; ni++)
            #pragma unroll
            for (int q = 0; q < 4; q++) acc[mi][ni][q] = 0.0f;

    for (int c = 0; c < NCHUNK; c++) {
        if (c > 0) __syncthreads();     // previous chunk fully consumed

        char* ahi = smem + SM_AHI;
        char* alo = smem + SM_ALO;

        // ---- build A chunk: h[e][64c .. 64c+64) split to bf16 hi/lo ----
        if (c < 4) {
            int zcol = (c < 2) ? zi_s[be] : zj_s[be];
            const float* src = emb + zcol * NF + (c & 1) * 64 + kh;
            #pragma unroll
            for (int g = 0; g < 8; g++) {
                float4 v = *(const float4*)(src + g * 4);
                store_split(v, ahi, alo, be * (PK * 2) + (kh + g * 4) * 2);
            }
        } else {
            const int fbase = (c - 4) * 64 + kh;
            float rr[NR];
            #pragma unroll
            for (int r = 0; r < NR; r++) rr[r] = rbf_s[be * NR + r];
            #pragma unroll
            for (int g = 0; g < 8; g++) {
                int f = fbase + g * 4;
                float4 a4 = *(const float4*)(b_rbf + f);
                #pragma unroll
                for (int r = 0; r < NR; r++) {
                    float4 w = *(const float4*)(W_rbf + r * NF + f);
                    a4.x = fmaf(rr[r], w.x, a4.x);
                    a4.y = fmaf(rr[r], w.y, a4.y);
                    a4.z = fmaf(rr[r], w.z, a4.z);
                    a4.w = fmaf(rr[r], w.w, a4.w);
                }
                a4.x = swishf(a4.x); a4.y = swishf(a4.y);
                a4.z = swishf(a4.z); a4.w = swishf(a4.w);
                store_split(a4, ahi, alo, be * (PK * 2) + (kh + g * 4) * 2);
            }
        }

        // ---- load B chunk (pre-split W^T) into padded smem ----
        {
            const uint4* shi = (const uint4*)(g_WT_hi + ((size_t)c * 128 + be) * KC + kh);
            const uint4* slo = (const uint4*)(g_WT_lo + ((size_t)c * 128 + be) * KC + kh);
            char* bhi = smem + SM_BHI;
            char* blo = smem + SM_BLO;
            #pragma unroll
            for (int g = 0; g < 4; g++) {
                int bo = be * (PK * 2) + kh * 2 + g * 16;
                *(uint4*)(bhi + bo) = shi[g];
                *(uint4*)(blo + bo) = slo[g];
            }
        }
        __syncthreads();

        // ---- MMA accumulate: 4 k16-steps x (hi.hi + hi.lo + lo.hi) ----
        #pragma unroll
        for (int ks = 0; ks < 4; ks++) {
            const int k0 = ks * 16;
            const uint32_t a_off = (uint32_t)((a_row * PK + k0 + a_kad) * 2);

            uint32_t ah[2][4], al[2][4];
            ldsm4(ahi_b + a_off,               ah[0][0], ah[0][1], ah[0][2], ah[0][3]);
            ldsm4(ahi_b + a_off + 16 * PK * 2, ah[1][0], ah[1][1], ah[1][2], ah[1][3]);
            ldsm4(alo_b + a_off,               al[0][0], al[0][1], al[0][2], al[0][3]);
            ldsm4(alo_b + a_off + 16 * PK * 2, al[1][0], al[1][1], al[1][2], al[1][3]);

            uint32_t bh[8][2], bl[8][2];
            #pragma unroll
            for (int nb = 0; nb < 4; nb++) {
                const uint32_t b_off =
                    (uint32_t)(((b_row + nb * 16) * PK + k0 + b_kad) * 2);
                ldsm4(bhi_b + b_off, bh[2 * nb][0], bh[2 * nb][1],
                                     bh[2 * nb + 1][0], bh[2 * nb + 1][1]);
                ldsm4(blo_b + b_off, bl[2 * nb][0], bl[2 * nb][1],
                                     bl[2 * nb + 1][0], bl[2 * nb + 1][1]);
            }

            #pragma unroll
            for (int mi = 0; mi < 2; mi++)
                #pragma unroll
                for (int ni = 0; ni < 8; ni++) {
                    mma_bf16(acc[mi][ni], ah[mi][0], ah[mi][1], ah[mi][2], ah[mi][3],
                             bh[ni][0], bh[ni][1]);
                    mma_bf16(acc[mi][ni], ah[mi][0], ah[mi][1], ah[mi][2], ah[mi][3],
                             bl[ni][0], bl[ni][1]);
                    mma_bf16(acc[mi][ni], al[mi][0], al[mi][1], al[mi][2], al[mi][3],
                             bh[ni][0], bh[ni][1]);
                }
        }
    }

    // ---- epilogue: +bias, swish, float2 stores ----
    // fragment map: c0,c1 at (row, col..col+1); c2,c3 at (row+8, same cols)
    const int r0 = wm * 32 + (lane >> 2);
    const int cbase = wn * 64 + (lane & 3) * 2;

    #pragma unroll
    for (int mi = 0; mi < 2; mi++) {
        const int rowA = base + r0 + mi * 16;
        const int rowB = rowA + 8;
        #pragma unroll
        for (int ni = 0; ni < 8; ni++) {
            const int col = cbase + ni * 8;
            float2 bv = *(const float2*)(bias + col);
            if (rowA < E) {
                float2 o;
                o.x = swishf(acc[mi][ni][0] + bv.x);
                o.y = swishf(acc[mi][ni][1] + bv.y);
                *(float2*)(out + (size_t)rowA * NF + col) = o;
            }
            if (rowB < E) {
                float2 o;
                o.x = swishf(acc[mi][ni][2] + bv.x);
                o.y = swishf(acc[mi][ni][3] + bv.y);
                *(float2*)(out + (size_t)rowB * NF + col) = o;
            }
        }
    }
}

extern "C" void kernel_launch(void* const* d_in, const int* in_sizes, int n_in,
                              void* d_out, int out_size) {
    const int*   Z      = (const int*)  d_in[0];
    const float* rbf    = (const float*)d_in[1];
    const int*   idnb_i = (const int*)  d_in[2];
    const int*   idnb_j = (const int*)  d_in[3];
    const float* emb    = (const float*)d_in[4];
    const float* W_rbf  = (const float*)d_in[5];
    const float* b_rbf  = (const float*)d_in[6];
    const float* W      = (const float*)d_in[7];
    const float* bias   = (const float*)d_in[8];
    float* out = (float*)d_out;

    const int E = in_sizes[2];

    // 1) split + transpose W into bf16 hi/lo chunk layout (runs every call)
    prep_w_kernel<<<(NCHUNK * 128 * KC + 255) / 256, 256>>>(W);

    // 2) fused gather + bf16-split mma.sync GEMM + swish
    cudaFuncSetAttribute(embedding_block_mma,
                         cudaFuncAttributeMaxDynamicSharedMemorySize, SM_BYTES);
    const int grid = (E + TILE_E - 1) / TILE_E;
    embedding_block_mma<<<grid, NTH, SM_BYTES>>>(
        Z, rbf, idnb_i, idnb_j, emb, W_rbf, b_rbf, bias, out, E);
}